// round 7
// baseline (speedup 1.0000x reference)
#include <cuda_runtime.h>
#include <stdint.h>

#define NROI    65536
#define NCASC   3
#define NBATCH  64
#define NROWS   (NBATCH * NCASC)
#define SLICES  8
#define SLICE_ELEMS (NROI / SLICES)        // 8192
#define SCAN_TPB 128
#define SCAN_WARPS (SCAN_TPB / 32)         // 4
#define WCHUNK  (SLICE_ELEMS / SCAN_WARPS) // 2048 elements per warp
#define A2_TPB  1024
#define PCAP    128                        // pos candidates per (row,slice)
#define NCAP    128                        // neg candidates per (row,slice)
#define BITWORDS (NROI / 32)               // 2048 words per row
#define TPOSC   0.99f
#define TNEGC   0.99f

#define NEG_LIST    0
#define NEG_ALLELIG 1
#define NEG_SLOW    2

struct Keys { uint32_t k0[3]; uint32_t k1[3]; };
struct RowPar { float mx, tk, top2, kth; int nopos, posfast, negmode; };

// per-(row,slice) partials — written unconditionally every run (no init pass)
__device__ float  g_pmax [NROWS * SLICES];
__device__ int    g_ppos [NROWS * SLICES];
__device__ int    g_pelig[NROWS * SLICES];
__device__ int    g_pcnt [NROWS * SLICES];
__device__ int    g_ncnt [NROWS * SLICES];
__device__ float  g_posv [NROWS * SLICES * PCAP];
__device__ int    g_posi [NROWS * SLICES * PCAP];
__device__ float  g_negu [NROWS * SLICES * NCAP];
__device__ int    g_negj [NROWS * SLICES * NCAP];
__device__ RowPar g_par  [NROWS];
__device__ unsigned g_negbit[NROWS * BITWORDS];   // 1.5 MB neg bitmap
__device__ unsigned g_posbit[NROWS * BITWORDS];   // 1.5 MB pos bitmap

__device__ const float c_POS_T[3] = {0.6f, 0.7f, 0.8f};
__device__ const float c_IOU_T[3] = {0.2f, 0.3f, 0.4f};
__device__ const float c_NEG_T[3] = {0.3f, 0.3f, 0.3f};

// ---------------------------------------------------------------------------
// JAX threefry2x32 (exact; verified rel_err = 0.0)
// ---------------------------------------------------------------------------
__host__ __device__ __forceinline__ void threefry2x32(
    uint32_t k0, uint32_t k1, uint32_t x0, uint32_t x1,
    uint32_t& o0, uint32_t& o1)
{
    uint32_t ks2 = k0 ^ k1 ^ 0x1BD11BDAu;
    x0 += k0; x1 += k1;
#define TFR(r) { x0 += x1; x1 = (x1 << (r)) | (x1 >> (32 - (r))); x1 ^= x0; }
    TFR(13) TFR(15) TFR(26) TFR(6)  x0 += k1;  x1 += ks2 + 1u;
    TFR(17) TFR(29) TFR(16) TFR(24) x0 += ks2; x1 += k0  + 2u;
    TFR(13) TFR(15) TFR(26) TFR(6)  x0 += k0;  x1 += k1  + 3u;
    TFR(17) TFR(29) TFR(16) TFR(24) x0 += k1;  x1 += ks2 + 4u;
    TFR(13) TFR(15) TFR(26) TFR(6)  x0 += ks2; x1 += k0  + 5u;
#undef TFR
    o0 = x0; o1 = x1;
}

__device__ __forceinline__ float u01(uint32_t k0, uint32_t k1, uint32_t idx)
{
    uint32_t a, c;
    threefry2x32(k0, k1, 0u, idx, a, c);
    uint32_t bits = a ^ c;
    return __uint_as_float((bits >> 9) | 0x3F800000u) - 1.0f;
}

// ---------------------------------------------------------------------------
// Block helpers (finalize kernel, 1024 threads)
// ---------------------------------------------------------------------------
__device__ __forceinline__ int block_reduce_sum_int(int v, int* sc)
{
    int tid = threadIdx.x;
    sc[tid] = v; __syncthreads();
    for (int s = A2_TPB / 2; s > 0; s >>= 1) {
        if (tid < s) sc[tid] += sc[tid + s];
        __syncthreads();
    }
    int r = sc[0];
    __syncthreads();
    return r;
}

__device__ void bitonic_desc(float* a)
{
    int tid = threadIdx.x;
    for (int k = 2; k <= A2_TPB; k <<= 1) {
        for (int j = k >> 1; j > 0; j >>= 1) {
            int ixj = tid ^ j;
            if (ixj > tid) {
                float x = a[tid], y = a[ixj];
                bool desc = ((tid & k) == 0);
                if (desc ? (x < y) : (x > y)) { a[tid] = y; a[ixj] = x; }
            }
            __syncthreads();
        }
    }
}

// ---------------------------------------------------------------------------
// Exact fallbacks (statistically never run; guarantee correctness)
// ---------------------------------------------------------------------------
__device__ float kth_bs_iomask(int k, const float* ov, const float* io,
                               float POS_T, int nopos, float mx, int* sc)
{
    unsigned lo = 0u, hi = 0x7F800000u;
    while (hi > lo) {
        unsigned mid = lo + ((hi - lo + 1u) >> 1);
        float t = __uint_as_float(mid);
        int c = 0;
        for (int j = threadIdx.x; j < NROI; j += A2_TPB) {
            float o = ov[j], v = io[j];
            float im = nopos ? ((v >= mx) ? v : 0.0f)
                             : ((o >= POS_T) ? v : 0.0f);
            c += (im >= t);
        }
        c = block_reduce_sum_int(c, sc);
        if (c >= k) lo = mid; else hi = mid - 1u;
    }
    return __uint_as_float(lo);
}

__device__ float kth_bs_score(int k, const float* ov, float NEG_T,
                              uint32_t k0, uint32_t k1, uint32_t rng_base, int* sc)
{
    unsigned lo = 0u, hi = 0x7F800000u;
    while (hi > lo) {
        unsigned mid = lo + ((hi - lo + 1u) >> 1);
        float t = __uint_as_float(mid);
        int c = 0;
        for (int j = threadIdx.x; j < NROI; j += A2_TPB) {
            float o = ov[j];
            if (o <= NEG_T) {
                float u = u01(k0, k1, rng_base + (uint32_t)j);
                c += (u >= t);
            }
        }
        c = block_reduce_sum_int(c, sc);
        if (c >= k) lo = mid; else hi = mid - 1u;
    }
    return __uint_as_float(lo);
}

// ---------------------------------------------------------------------------
// Kernel A: scan. grid = NROWS*SLICES, 128 threads (4 warps x 2048 elements).
// Worst-case-sized per-warp smem queue: no atomics, no overflow, no divergence.
// ---------------------------------------------------------------------------
__global__ __launch_bounds__(SCAN_TPB)
void scan_kernel(const float* __restrict__ g_ov,
                 const float* __restrict__ g_io,
                 Keys keys)
{
    __shared__ uint16_t s_q[SCAN_WARPS][WCHUNK];   // 16 KB
    __shared__ int   s_cp, s_cn;
    __shared__ float s_wmax[SCAN_WARPS];
    __shared__ int   s_wpos[SCAN_WARPS];
    __shared__ int   s_welig[SCAN_WARPS];

    const int tid   = threadIdx.x;
    const int wid   = tid >> 5;
    const int lane  = tid & 31;
    const int blk   = blockIdx.x;
    const int r     = blk >> 3;
    const int slice = blk & (SLICES - 1);
    const int h     = r % 3;
    const int b     = r / 3;

    const float POS_T = c_POS_T[h];
    const float NEG_T = c_NEG_T[h];
    const uint32_t k0 = keys.k0[h];
    const uint32_t k1 = keys.k1[h];
    const uint32_t rng_base = (uint32_t)b * (uint32_t)NROI;

    if (tid == 0) { s_cp = 0; s_cn = 0; }
    __syncthreads();

    const int chunk0 = slice * SLICE_ELEMS + wid * WCHUNK;
    const float4* ov4 = (const float4*)(g_ov + (size_t)r * NROI) + (chunk0 >> 2);
    const float4* io4 = (const float4*)(g_io + (size_t)r * NROI) + (chunk0 >> 2);

    const unsigned lmask = (1u << lane) - 1u;
    float lmax = 0.0f;
    int lpos = 0;
    int cnt = 0;

    // ---------- Phase A: scan + compact to smem queue ----------
#pragma unroll 4
    for (int it = 0; it < WCHUNK / 4 / 32; it++) {   // 16 iters
        int q = it * 32 + lane;
        float4 o4 = ov4[q];
        float4 v4 = io4[q];
        int local = q * 4;
#pragma unroll
        for (int l = 0; l < 4; l++) {
            float o = (&o4.x)[l];
            float v = (&v4.x)[l];
            lmax = fmaxf(lmax, v);
            bool pm = (o >= POS_T);
            lpos += pm;
            if (pm && v >= TPOSC) {                 // ~0.4% of elements
                int p = atomicAdd(&s_cp, 1);
                if (p < PCAP) {
                    g_posv[blk * PCAP + p] = v;
                    g_posi[blk * PCAP + p] = chunk0 + local + l;
                }
            }
            bool el = (o <= NEG_T);
            unsigned m = __ballot_sync(0xFFFFFFFFu, el);
            if (el) s_q[wid][cnt + __popc(m & lmask)] = (uint16_t)(local + l);
            cnt += __popc(m);
        }
    }
    __syncwarp();

    // ---------- Phase B: dense hashing of compacted queue ----------
    const uint32_t jwbase = rng_base + (uint32_t)chunk0;
    for (int t = lane; t < cnt; t += 32) {
        uint32_t idx = (uint32_t)s_q[wid][t];
        float u = u01(k0, k1, jwbase + idx);
        if (u >= TNEGC) {                           // ~1% of eligible
            int p = atomicAdd(&s_cn, 1);
            if (p < NCAP) {
                g_negu[blk * NCAP + p] = u;
                g_negj[blk * NCAP + p] = (int)(chunk0 + idx);
            }
        }
    }

    // ---------- reductions ----------
    unsigned wmaxb = __reduce_max_sync(0xFFFFFFFFu, __float_as_uint(lmax));
    unsigned wpos  = __reduce_add_sync(0xFFFFFFFFu, (unsigned)lpos);
    if (lane == 0) {
        s_wmax[wid]  = __uint_as_float(wmaxb);
        s_wpos[wid]  = (int)wpos;
        s_welig[wid] = cnt;
    }
    __syncthreads();
    if (tid == 0) {
        float mx = 0.0f; int pc = 0, ec = 0;
#pragma unroll
        for (int w = 0; w < SCAN_WARPS; w++) {
            mx = fmaxf(mx, s_wmax[w]);
            pc += s_wpos[w];
            ec += s_welig[w];
        }
        g_pmax[blk] = mx;
        g_ppos[blk] = pc;
        g_pelig[blk] = ec;
        g_pcnt[blk] = s_cp;
        g_ncnt[blk] = s_cn;
    }
}

// ---------------------------------------------------------------------------
// Kernel B: per-row finalize. grid = NROWS, 1024 threads.
// Computes thresholds and writes pos + neg bitmaps.
// ---------------------------------------------------------------------------
__global__ __launch_bounds__(A2_TPB)
void finalize_kernel(const float* __restrict__ g_ov,
                     const float* __restrict__ g_io,
                     Keys keys)
{
    __shared__ float s_sort[A2_TPB];
    __shared__ int   s_pcnt[SLICES], s_ncnt[SLICES];
    __shared__ float s_mx8[SLICES];
    __shared__ int   s_pos8[SLICES], s_elig8[SLICES];
    __shared__ float s_mx;
    __shared__ int   s_poscnt, s_eligcnt, s_cp, s_cn, s_ovfP, s_ovfN;

    const int tid = threadIdx.x;
    const int r = blockIdx.x;
    const int h = r % 3;
    const int b = r / 3;

    const float POS_T = c_POS_T[h];
    const float NEG_T = c_NEG_T[h];
    const float IOU_T = c_IOU_T[h];
    const uint32_t k0 = keys.k0[h];
    const uint32_t k1 = keys.k1[h];
    const uint32_t rng_base = (uint32_t)b * (uint32_t)NROI;

    const float* ov = g_ov + (size_t)r * NROI;
    const float* io = g_io + (size_t)r * NROI;

    // zero both bitmaps for this row (before any atomicOr)
    for (int i2 = tid; i2 < BITWORDS; i2 += A2_TPB) {
        g_negbit[r * BITWORDS + i2] = 0u;
        g_posbit[r * BITWORDS + i2] = 0u;
    }

    if (tid < SLICES) {
        int blk = r * SLICES + tid;
        s_pcnt[tid] = g_pcnt[blk];
        s_ncnt[tid] = g_ncnt[blk];
        s_mx8[tid]  = g_pmax[blk];
        s_pos8[tid] = g_ppos[blk];
        s_elig8[tid]= g_pelig[blk];
    }
    __syncthreads();
    if (tid == 0) {
        float mx = 0.0f; int pc = 0, ec = 0, cp = 0, cn = 0, op = 0, on = 0;
#pragma unroll
        for (int s = 0; s < SLICES; s++) {
            mx = fmaxf(mx, s_mx8[s]); pc += s_pos8[s]; ec += s_elig8[s];
            cp += s_pcnt[s]; cn += s_ncnt[s];
            op |= (s_pcnt[s] > PCAP); on |= (s_ncnt[s] > NCAP);
        }
        s_mx = mx; s_poscnt = pc; s_eligcnt = ec;
        s_cp = cp; s_cn = cn; s_ovfP = op; s_ovfN = on;
    }
    __syncthreads();

    const float mx = s_mx;
    const int poscnt = s_poscnt, eligcnt = s_eligcnt;
    const int cp = s_cp, cn = s_cn, ovfP = s_ovfP, ovfN = s_ovfN;

    // -------- positive threshold: 16th (+2nd) largest of iou_masked --------
    int nopos = (poscnt == 0);
    int posfast = 0;
    float t16, top2 = 0.0f;
    if (!nopos && cp >= 16 && !ovfP) {
        posfast = 1;
        int sl = tid >> 7, i = tid & (PCAP - 1);
        bool valid = (i < s_pcnt[sl]);
        float v_reg = valid ? g_posv[(r * SLICES + sl) * PCAP + i] : -1.0f;
        int   j_reg = valid ? g_posi[(r * SLICES + sl) * PCAP + i] : 0;
        s_sort[tid] = v_reg;
        __syncthreads();
        bitonic_desc(s_sort);
        t16 = s_sort[15];
        top2 = s_sort[1];
        __syncthreads();
        // pos bits: im >= tk (tk = t16 >= TPOSC >= IOU_T here), plus h=0 top2 OR
        float tkf = (t16 >= IOU_T) ? t16 : IOU_T;
        bool posb = valid && ((v_reg >= tkf) || (h == 0 && v_reg > top2));
        if (posb)
            atomicOr(&g_posbit[r * BITWORDS + (j_reg >> 5)], 1u << (j_reg & 31));
    } else {
        t16 = kth_bs_iomask(16, ov, io, POS_T, nopos, mx, (int*)s_sort);
        if (h == 0) top2 = kth_bs_iomask(2, ov, io, POS_T, nopos, mx, (int*)s_sort);
    }
    float tk = (t16 >= IOU_T) ? t16 : IOU_T;

    // -------- negative threshold: 48th largest random score among eligible --
    float kth = -1.0f;
    int negmode;
    if (eligcnt < 48) {
        negmode = NEG_ALLELIG;               // kth = -inf: all eligible neg
    } else if (cn >= 48 && !ovfN) {
        negmode = NEG_LIST;
        int sl = tid >> 7, i = tid & (NCAP - 1);
        bool valid = (i < s_ncnt[sl]);
        float u_reg = valid ? g_negu[(r * SLICES + sl) * NCAP + i] : -1.0f;
        int   j_reg = valid ? g_negj[(r * SLICES + sl) * NCAP + i] : 0;
        s_sort[tid] = u_reg;
        __syncthreads();
        bitonic_desc(s_sort);
        kth = s_sort[47];
        __syncthreads();
        if (valid && u_reg >= kth)
            atomicOr(&g_negbit[r * BITWORDS + (j_reg >> 5)], 1u << (j_reg & 31));
    } else {
        negmode = NEG_SLOW;
        kth = kth_bs_score(48, ov, NEG_T, k0, k1, rng_base, (int*)s_sort);
    }

    if (tid == 0) {
        RowPar p;
        p.mx = mx; p.tk = tk; p.top2 = top2; p.kth = kth;
        p.nopos = nopos; p.posfast = posfast; p.negmode = negmode;
        g_par[r] = p;
    }
}

// ---------------------------------------------------------------------------
// Kernel C: labels. Fast rows read ONLY the two bitmaps (no ov/io traffic).
// grid = NROWS*8, 256 threads; each thread owns 32 consecutive elements.
// ---------------------------------------------------------------------------
__global__ __launch_bounds__(256)
void label_kernel(const float* __restrict__ g_ov,
                  const float* __restrict__ g_io,
                  const float* __restrict__ g_nm,
                  float* __restrict__ g_out,
                  Keys keys)
{
    const int tid = threadIdx.x;
    const int r = blockIdx.x >> 3;
    const int chunk = blockIdx.x & 7;
    const int h = r % 3;
    const int g = chunk * 256 + tid;          // 32-elem group within row
    const int jb = g * 32;                    // row-relative element base

    RowPar p = g_par[r];
    const float* nm = g_nm + (size_t)r * NROI;
    float4* out4 = (float4*)(g_out + (size_t)r * NROI);

    if (p.posfast && p.negmode == NEG_LIST) {
        // ---- fast path: bitmaps only ----
        unsigned negw = g_negbit[r * BITWORDS + g];
        unsigned posw = g_posbit[r * BITWORDS + g];
#pragma unroll
        for (int w = 0; w < 8; w++) {
            float4 res;
#pragma unroll
            for (int l = 0; l < 4; l++) {
                int bit = w * 4 + l;
                float negf = (float)((negw >> bit) & 1u);
                float posf = 0.0f;
                if ((posw >> bit) & 1u) posf = nm[jb + bit];   // rare
                (&res.x)[l] = (-1.0f + negf) + 2.0f * posf;
            }
            out4[g * 8 + w] = res;
        }
        return;
    }

    // ---- full path (statistically never; exact) ----
    const float POS_T = c_POS_T[h];
    const float NEG_T = c_NEG_T[h];
    const uint32_t rng_base = (uint32_t)(r / 3) * (uint32_t)NROI;
    const float4* ov4 = (const float4*)(g_ov + (size_t)r * NROI);
    const float4* io4 = (const float4*)(g_io + (size_t)r * NROI);
    unsigned negw = (p.negmode == NEG_LIST) ? g_negbit[r * BITWORDS + g] : 0u;

#pragma unroll
    for (int w = 0; w < 8; w++) {
        int q = g * 8 + w;
        float4 o4 = ov4[q];
        float4 v4 = io4[q];
        float4 res;
#pragma unroll
        for (int l = 0; l < 4; l++) {
            int bit = w * 4 + l;
            float o = (&o4.x)[l];
            float v = (&v4.x)[l];
            float im = p.nopos ? ((v >= p.mx) ? v : 0.0f)
                               : ((o >= POS_T) ? v : 0.0f);
            bool posb = (im >= p.tk);
            if (h == 0) posb = posb || (im > p.top2);
            float posf = 0.0f;
            if (posb) posf = nm[jb + bit];

            float negf;
            if (p.negmode == NEG_LIST) {
                negf = (float)((negw >> bit) & 1u);
            } else if (p.negmode == NEG_ALLELIG) {
                negf = (o <= NEG_T) ? 1.0f : 0.0f;
            } else {
                negf = 0.0f;
                if (o <= NEG_T) {
                    float u = u01(keys.k0[h], keys.k1[h],
                                  rng_base + (uint32_t)(jb + bit));
                    if (u >= p.kth) negf = 1.0f;
                }
            }
            (&res.x)[l] = (-1.0f + negf) + 2.0f * posf;
        }
        out4[q] = res;
    }
}

// ---------------------------------------------------------------------------
// Launch
// ---------------------------------------------------------------------------
extern "C" void kernel_launch(void* const* d_in, const int* in_sizes, int n_in,
                              void* d_out, int out_size)
{
    const float* ov = (const float*)d_in[0];
    const float* io = (const float*)d_in[1];
    const float* nm = (const float*)d_in[2];
    float* out = (float*)d_out;

    Keys keys;
    for (int h = 0; h < NCASC; h++) {
        uint32_t a, c;
        threefry2x32(0u, 42u, 0u, (uint32_t)h, a, c);
        keys.k0[h] = a;
        keys.k1[h] = c;
    }

    scan_kernel<<<NROWS * SLICES, SCAN_TPB>>>(ov, io, keys);
    finalize_kernel<<<NROWS, A2_TPB>>>(ov, io, keys);
    label_kernel<<<NROWS * 8, 256>>>(ov, io, nm, out, keys);
}

// round 8
// speedup vs baseline: 1.1536x; 1.1536x over previous
#include <cuda_runtime.h>
#include <stdint.h>

#define NROI    65536
#define NCASC   3
#define NBATCH  64
#define NROWS   (NBATCH * NCASC)
#define SLICES  16
#define SLICE_ELEMS (NROI / SLICES)        // 4096
#define SCAN_TPB 128
#define SCAN_WARPS (SCAN_TPB / 32)         // 4
#define WCHUNK  (SLICE_ELEMS / SCAN_WARPS) // 1024 elements per warp
#define A2_TPB  1024
#define PCAP    64                         // pos candidates per (row,slice)
#define NCAP    64                         // neg candidates per (row,slice)
#define BITWORDS (NROI / 32)               // 2048 words per row
#define TPOSC   0.99f
#define TNEGC   0.99f

#define NEG_LIST    0
#define NEG_ALLELIG 1
#define NEG_SLOW    2

struct Keys { uint32_t k0[3]; uint32_t k1[3]; };
struct RowPar { float mx, tk, top2, kth; int nopos, posfast, negmode; };

// per-(row,slice) partials — written unconditionally every run (no init pass)
__device__ float  g_pmax [NROWS * SLICES];
__device__ int    g_ppos [NROWS * SLICES];
__device__ int    g_pelig[NROWS * SLICES];
__device__ int    g_pcnt [NROWS * SLICES];
__device__ int    g_ncnt [NROWS * SLICES];
__device__ float  g_posv [NROWS * SLICES * PCAP];
__device__ int    g_posi [NROWS * SLICES * PCAP];
__device__ float  g_negu [NROWS * SLICES * NCAP];
__device__ int    g_negj [NROWS * SLICES * NCAP];
__device__ RowPar g_par  [NROWS];
__device__ unsigned g_negbit[NROWS * BITWORDS];   // 1.5 MB neg bitmap
__device__ unsigned g_posbit[NROWS * BITWORDS];   // 1.5 MB pos bitmap

__device__ const float c_POS_T[3] = {0.6f, 0.7f, 0.8f};
__device__ const float c_IOU_T[3] = {0.2f, 0.3f, 0.4f};
__device__ const float c_NEG_T[3] = {0.3f, 0.3f, 0.3f};

// ---------------------------------------------------------------------------
// JAX threefry2x32 (exact; verified rel_err = 0.0)
// ---------------------------------------------------------------------------
__host__ __device__ __forceinline__ void threefry2x32(
    uint32_t k0, uint32_t k1, uint32_t x0, uint32_t x1,
    uint32_t& o0, uint32_t& o1)
{
    uint32_t ks2 = k0 ^ k1 ^ 0x1BD11BDAu;
    x0 += k0; x1 += k1;
#define TFR(r) { x0 += x1; x1 = (x1 << (r)) | (x1 >> (32 - (r))); x1 ^= x0; }
    TFR(13) TFR(15) TFR(26) TFR(6)  x0 += k1;  x1 += ks2 + 1u;
    TFR(17) TFR(29) TFR(16) TFR(24) x0 += ks2; x1 += k0  + 2u;
    TFR(13) TFR(15) TFR(26) TFR(6)  x0 += k0;  x1 += k1  + 3u;
    TFR(17) TFR(29) TFR(16) TFR(24) x0 += k1;  x1 += ks2 + 4u;
    TFR(13) TFR(15) TFR(26) TFR(6)  x0 += ks2; x1 += k0  + 5u;
#undef TFR
    o0 = x0; o1 = x1;
}

__device__ __forceinline__ float u01(uint32_t k0, uint32_t k1, uint32_t idx)
{
    uint32_t a, c;
    threefry2x32(k0, k1, 0u, idx, a, c);
    uint32_t bits = a ^ c;
    return __uint_as_float((bits >> 9) | 0x3F800000u) - 1.0f;
}

// ---------------------------------------------------------------------------
// Block helpers (finalize kernel, 1024 threads)
// ---------------------------------------------------------------------------
__device__ __forceinline__ int block_reduce_sum_int(int v, int* sc)
{
    int tid = threadIdx.x;
    sc[tid] = v; __syncthreads();
    for (int s = A2_TPB / 2; s > 0; s >>= 1) {
        if (tid < s) sc[tid] += sc[tid + s];
        __syncthreads();
    }
    int r = sc[0];
    __syncthreads();
    return r;
}

__device__ void bitonic_desc(float* a)
{
    int tid = threadIdx.x;
    for (int k = 2; k <= A2_TPB; k <<= 1) {
        for (int j = k >> 1; j > 0; j >>= 1) {
            int ixj = tid ^ j;
            if (ixj > tid) {
                float x = a[tid], y = a[ixj];
                bool desc = ((tid & k) == 0);
                if (desc ? (x < y) : (x > y)) { a[tid] = y; a[ixj] = x; }
            }
            __syncthreads();
        }
    }
}

// ---------------------------------------------------------------------------
// Exact fallbacks (statistically never run; guarantee correctness)
// ---------------------------------------------------------------------------
__device__ float kth_bs_iomask(int k, const float* ov, const float* io,
                               float POS_T, int nopos, float mx, int* sc)
{
    unsigned lo = 0u, hi = 0x7F800000u;
    while (hi > lo) {
        unsigned mid = lo + ((hi - lo + 1u) >> 1);
        float t = __uint_as_float(mid);
        int c = 0;
        for (int j = threadIdx.x; j < NROI; j += A2_TPB) {
            float o = ov[j], v = io[j];
            float im = nopos ? ((v >= mx) ? v : 0.0f)
                             : ((o >= POS_T) ? v : 0.0f);
            c += (im >= t);
        }
        c = block_reduce_sum_int(c, sc);
        if (c >= k) lo = mid; else hi = mid - 1u;
    }
    return __uint_as_float(lo);
}

__device__ float kth_bs_score(int k, const float* ov, float NEG_T,
                              uint32_t k0, uint32_t k1, uint32_t rng_base, int* sc)
{
    unsigned lo = 0u, hi = 0x7F800000u;
    while (hi > lo) {
        unsigned mid = lo + ((hi - lo + 1u) >> 1);
        float t = __uint_as_float(mid);
        int c = 0;
        for (int j = threadIdx.x; j < NROI; j += A2_TPB) {
            float o = ov[j];
            if (o <= NEG_T) {
                float u = u01(k0, k1, rng_base + (uint32_t)j);
                c += (u >= t);
            }
        }
        c = block_reduce_sum_int(c, sc);
        if (c >= k) lo = mid; else hi = mid - 1u;
    }
    return __uint_as_float(lo);
}

// ---------------------------------------------------------------------------
// Kernel A: scan. grid = NROWS*SLICES = 3072 blocks, 128 threads.
// 4 warps x 1024 elements; worst-case-sized per-warp smem queue (8 KB/block
// -> 16 resident blocks/SM = full occupancy).
// ---------------------------------------------------------------------------
__global__ __launch_bounds__(SCAN_TPB)
void scan_kernel(const float* __restrict__ g_ov,
                 const float* __restrict__ g_io,
                 Keys keys)
{
    __shared__ uint16_t s_q[SCAN_WARPS][WCHUNK];   // 8 KB
    __shared__ int   s_cp, s_cn;
    __shared__ float s_wmax[SCAN_WARPS];
    __shared__ int   s_wpos[SCAN_WARPS];
    __shared__ int   s_welig[SCAN_WARPS];

    const int tid   = threadIdx.x;
    const int wid   = tid >> 5;
    const int lane  = tid & 31;
    const int blk   = blockIdx.x;
    const int r     = blk >> 4;
    const int slice = blk & (SLICES - 1);
    const int h     = r % 3;
    const int b     = r / 3;

    const float POS_T = c_POS_T[h];
    const float NEG_T = c_NEG_T[h];
    const uint32_t k0 = keys.k0[h];
    const uint32_t k1 = keys.k1[h];
    const uint32_t rng_base = (uint32_t)b * (uint32_t)NROI;

    if (tid == 0) { s_cp = 0; s_cn = 0; }
    __syncthreads();

    const int chunk0 = slice * SLICE_ELEMS + wid * WCHUNK;
    const float4* ov4 = (const float4*)(g_ov + (size_t)r * NROI) + (chunk0 >> 2);
    const float4* io4 = (const float4*)(g_io + (size_t)r * NROI) + (chunk0 >> 2);

    const unsigned lmask = (1u << lane) - 1u;
    float lmax = 0.0f;
    int lpos = 0;
    int cnt = 0;

    // ---------- Phase A: scan + compact to smem queue ----------
#pragma unroll 4
    for (int it = 0; it < WCHUNK / 4 / 32; it++) {   // 8 iters
        int q = it * 32 + lane;
        float4 o4 = ov4[q];
        float4 v4 = io4[q];
        int local = q * 4;
#pragma unroll
        for (int l = 0; l < 4; l++) {
            float o = (&o4.x)[l];
            float v = (&v4.x)[l];
            lmax = fmaxf(lmax, v);
            bool pm = (o >= POS_T);
            lpos += pm;
            if (pm && v >= TPOSC) {                 // ~0.4% of elements
                int p = atomicAdd(&s_cp, 1);
                if (p < PCAP) {
                    g_posv[blk * PCAP + p] = v;
                    g_posi[blk * PCAP + p] = chunk0 + local + l;
                }
            }
            bool el = (o <= NEG_T);
            unsigned m = __ballot_sync(0xFFFFFFFFu, el);
            if (el) s_q[wid][cnt + __popc(m & lmask)] = (uint16_t)(local + l);
            cnt += __popc(m);
        }
    }
    __syncwarp();

    // ---------- Phase B: dense hashing of compacted queue ----------
    const uint32_t jwbase = rng_base + (uint32_t)chunk0;
    for (int t = lane; t < cnt; t += 32) {
        uint32_t idx = (uint32_t)s_q[wid][t];
        float u = u01(k0, k1, jwbase + idx);
        if (u >= TNEGC) {                           // ~1% of eligible
            int p = atomicAdd(&s_cn, 1);
            if (p < NCAP) {
                g_negu[blk * NCAP + p] = u;
                g_negj[blk * NCAP + p] = (int)(chunk0 + idx);
            }
        }
    }

    // ---------- reductions ----------
    unsigned wmaxb = __reduce_max_sync(0xFFFFFFFFu, __float_as_uint(lmax));
    unsigned wpos  = __reduce_add_sync(0xFFFFFFFFu, (unsigned)lpos);
    if (lane == 0) {
        s_wmax[wid]  = __uint_as_float(wmaxb);
        s_wpos[wid]  = (int)wpos;
        s_welig[wid] = cnt;
    }
    __syncthreads();
    if (tid == 0) {
        float mx = 0.0f; int pc = 0, ec = 0;
#pragma unroll
        for (int w = 0; w < SCAN_WARPS; w++) {
            mx = fmaxf(mx, s_wmax[w]);
            pc += s_wpos[w];
            ec += s_welig[w];
        }
        g_pmax[blk] = mx;
        g_ppos[blk] = pc;
        g_pelig[blk] = ec;
        g_pcnt[blk] = s_cp;
        g_ncnt[blk] = s_cn;
    }
}

// ---------------------------------------------------------------------------
// Kernel B: per-row finalize. grid = NROWS, 1024 threads.
// Computes thresholds and writes pos + neg bitmaps.
// ---------------------------------------------------------------------------
__global__ __launch_bounds__(A2_TPB)
void finalize_kernel(const float* __restrict__ g_ov,
                     const float* __restrict__ g_io,
                     Keys keys)
{
    __shared__ float s_sort[A2_TPB];
    __shared__ int   s_pcnt[SLICES], s_ncnt[SLICES];
    __shared__ float s_mxs[SLICES];
    __shared__ int   s_poss[SLICES], s_eligs[SLICES];
    __shared__ float s_mx;
    __shared__ int   s_poscnt, s_eligcnt, s_cp, s_cn, s_ovfP, s_ovfN;

    const int tid = threadIdx.x;
    const int r = blockIdx.x;
    const int h = r % 3;
    const int b = r / 3;

    const float POS_T = c_POS_T[h];
    const float NEG_T = c_NEG_T[h];
    const float IOU_T = c_IOU_T[h];
    const uint32_t k0 = keys.k0[h];
    const uint32_t k1 = keys.k1[h];
    const uint32_t rng_base = (uint32_t)b * (uint32_t)NROI;

    const float* ov = g_ov + (size_t)r * NROI;
    const float* io = g_io + (size_t)r * NROI;

    // zero both bitmaps for this row (before any atomicOr)
    for (int i2 = tid; i2 < BITWORDS; i2 += A2_TPB) {
        g_negbit[r * BITWORDS + i2] = 0u;
        g_posbit[r * BITWORDS + i2] = 0u;
    }

    if (tid < SLICES) {
        int blk = r * SLICES + tid;
        s_pcnt[tid] = g_pcnt[blk];
        s_ncnt[tid] = g_ncnt[blk];
        s_mxs[tid]  = g_pmax[blk];
        s_poss[tid] = g_ppos[blk];
        s_eligs[tid]= g_pelig[blk];
    }
    __syncthreads();
    if (tid == 0) {
        float mx = 0.0f; int pc = 0, ec = 0, cp = 0, cn = 0, op = 0, on = 0;
#pragma unroll
        for (int s = 0; s < SLICES; s++) {
            mx = fmaxf(mx, s_mxs[s]); pc += s_poss[s]; ec += s_eligs[s];
            cp += s_pcnt[s]; cn += s_ncnt[s];
            op |= (s_pcnt[s] > PCAP); on |= (s_ncnt[s] > NCAP);
        }
        s_mx = mx; s_poscnt = pc; s_eligcnt = ec;
        s_cp = cp; s_cn = cn; s_ovfP = op; s_ovfN = on;
    }
    __syncthreads();

    const float mx = s_mx;
    const int poscnt = s_poscnt, eligcnt = s_eligcnt;
    const int cp = s_cp, cn = s_cn, ovfP = s_ovfP, ovfN = s_ovfN;

    // -------- positive threshold: 16th (+2nd) largest of iou_masked --------
    int nopos = (poscnt == 0);
    int posfast = 0;
    float t16, top2 = 0.0f;
    if (!nopos && cp >= 16 && !ovfP) {
        posfast = 1;
        int sl = tid >> 6, i = tid & (PCAP - 1);
        bool valid = (i < s_pcnt[sl]);
        float v_reg = valid ? g_posv[(r * SLICES + sl) * PCAP + i] : -1.0f;
        int   j_reg = valid ? g_posi[(r * SLICES + sl) * PCAP + i] : 0;
        s_sort[tid] = v_reg;
        __syncthreads();
        bitonic_desc(s_sort);
        t16 = s_sort[15];
        top2 = s_sort[1];
        __syncthreads();
        float tkf = (t16 >= IOU_T) ? t16 : IOU_T;
        bool posb = valid && ((v_reg >= tkf) || (h == 0 && v_reg > top2));
        if (posb)
            atomicOr(&g_posbit[r * BITWORDS + (j_reg >> 5)], 1u << (j_reg & 31));
    } else {
        t16 = kth_bs_iomask(16, ov, io, POS_T, nopos, mx, (int*)s_sort);
        if (h == 0) top2 = kth_bs_iomask(2, ov, io, POS_T, nopos, mx, (int*)s_sort);
    }
    float tk = (t16 >= IOU_T) ? t16 : IOU_T;

    // -------- negative threshold: 48th largest random score among eligible --
    float kth = -1.0f;
    int negmode;
    if (eligcnt < 48) {
        negmode = NEG_ALLELIG;               // kth = -inf: all eligible neg
    } else if (cn >= 48 && !ovfN) {
        negmode = NEG_LIST;
        int sl = tid >> 6, i = tid & (NCAP - 1);
        bool valid = (i < s_ncnt[sl]);
        float u_reg = valid ? g_negu[(r * SLICES + sl) * NCAP + i] : -1.0f;
        int   j_reg = valid ? g_negj[(r * SLICES + sl) * NCAP + i] : 0;
        s_sort[tid] = u_reg;
        __syncthreads();
        bitonic_desc(s_sort);
        kth = s_sort[47];
        __syncthreads();
        if (valid && u_reg >= kth)
            atomicOr(&g_negbit[r * BITWORDS + (j_reg >> 5)], 1u << (j_reg & 31));
    } else {
        negmode = NEG_SLOW;
        kth = kth_bs_score(48, ov, NEG_T, k0, k1, rng_base, (int*)s_sort);
    }

    if (tid == 0) {
        RowPar p;
        p.mx = mx; p.tk = tk; p.top2 = top2; p.kth = kth;
        p.nopos = nopos; p.posfast = posfast; p.negmode = negmode;
        g_par[r] = p;
    }
}

// ---------------------------------------------------------------------------
// Kernel C: labels, fully coalesced. Consecutive threads own consecutive
// float4s; bitmap word for float4 q is bit[q>>3] (L1-broadcast across the
// 8 threads sharing it). Fast rows touch no ov/io at all.
// grid = NROWS*32, 256 threads, 2 float4 per thread.
// ---------------------------------------------------------------------------
__global__ __launch_bounds__(256)
void label_kernel(const float* __restrict__ g_ov,
                  const float* __restrict__ g_io,
                  const float* __restrict__ g_nm,
                  float* __restrict__ g_out,
                  Keys keys)
{
    const int tid = threadIdx.x;
    const int r = blockIdx.x >> 5;
    const int chunk = blockIdx.x & 31;
    const int h = r % 3;

    RowPar p = g_par[r];
    const float* nm = g_nm + (size_t)r * NROI;
    float4* out4 = (float4*)(g_out + (size_t)r * NROI);
    const unsigned* negbit = g_negbit + r * BITWORDS;
    const unsigned* posbit = g_posbit + r * BITWORDS;

    const int qa = chunk * 512 + tid;         // row-relative float4 index
    const int qb = qa + 256;

    if (p.posfast && p.negmode == NEG_LIST) {
        // ---- fast path: bitmaps only ----
#pragma unroll
        for (int half = 0; half < 2; half++) {
            int q = half ? qb : qa;
            int sh = (q & 7) * 4;
            unsigned nn = (negbit[q >> 3] >> sh) & 0xFu;
            unsigned pn = (posbit[q >> 3] >> sh) & 0xFu;
            float4 res;
#pragma unroll
            for (int l = 0; l < 4; l++) {
                float negf = (float)((nn >> l) & 1u);
                float posf = 0.0f;
                if ((pn >> l) & 1u) posf = nm[q * 4 + l];   // rare
                (&res.x)[l] = (-1.0f + negf) + 2.0f * posf;
            }
            out4[q] = res;
        }
        return;
    }

    // ---- full path (statistically never; exact) ----
    const float POS_T = c_POS_T[h];
    const float NEG_T = c_NEG_T[h];
    const uint32_t rng_base = (uint32_t)(r / 3) * (uint32_t)NROI;
    const float4* ov4 = (const float4*)(g_ov + (size_t)r * NROI);
    const float4* io4 = (const float4*)(g_io + (size_t)r * NROI);

#pragma unroll
    for (int half = 0; half < 2; half++) {
        int q = half ? qb : qa;
        float4 o4 = ov4[q];
        float4 v4 = io4[q];
        unsigned nn = 0u;
        if (p.negmode == NEG_LIST)
            nn = (negbit[q >> 3] >> ((q & 7) * 4)) & 0xFu;
        float4 res;
#pragma unroll
        for (int l = 0; l < 4; l++) {
            float o = (&o4.x)[l];
            float v = (&v4.x)[l];
            float im = p.nopos ? ((v >= p.mx) ? v : 0.0f)
                               : ((o >= POS_T) ? v : 0.0f);
            bool posb = (im >= p.tk);
            if (h == 0) posb = posb || (im > p.top2);
            float posf = 0.0f;
            if (posb) posf = nm[q * 4 + l];

            float negf;
            if (p.negmode == NEG_LIST) {
                negf = (float)((nn >> l) & 1u);
            } else if (p.negmode == NEG_ALLELIG) {
                negf = (o <= NEG_T) ? 1.0f : 0.0f;
            } else {
                negf = 0.0f;
                if (o <= NEG_T) {
                    float u = u01(keys.k0[h], keys.k1[h],
                                  rng_base + (uint32_t)(q * 4 + l));
                    if (u >= p.kth) negf = 1.0f;
                }
            }
            (&res.x)[l] = (-1.0f + negf) + 2.0f * posf;
        }
        out4[q] = res;
    }
}

// ---------------------------------------------------------------------------
// Launch
// ---------------------------------------------------------------------------
extern "C" void kernel_launch(void* const* d_in, const int* in_sizes, int n_in,
                              void* d_out, int out_size)
{
    const float* ov = (const float*)d_in[0];
    const float* io = (const float*)d_in[1];
    const float* nm = (const float*)d_in[2];
    float* out = (float*)d_out;

    Keys keys;
    for (int h = 0; h < NCASC; h++) {
        uint32_t a, c;
        threefry2x32(0u, 42u, 0u, (uint32_t)h, a, c);
        keys.k0[h] = a;
        keys.k1[h] = c;
    }

    scan_kernel<<<NROWS * SLICES, SCAN_TPB>>>(ov, io, keys);
    finalize_kernel<<<NROWS, A2_TPB>>>(ov, io, keys);
    label_kernel<<<NROWS * 32, 256>>>(ov, io, nm, out, keys);
}

// round 9
// speedup vs baseline: 1.2993x; 1.1263x over previous
#include <cuda_runtime.h>
#include <stdint.h>

#define NROI    65536
#define NCASC   3
#define NBATCH  64
#define NROWS   (NBATCH * NCASC)
#define SLICES  16
#define SLICE_ELEMS (NROI / SLICES)        // 4096
#define SCAN_TPB 128
#define SCAN_WARPS (SCAN_TPB / 32)         // 4
#define WCHUNK  (SLICE_ELEMS / SCAN_WARPS) // 1024 elements per warp
#define A2_TPB  1024
#define PCAP    64                         // pos candidates per (row,slice)
#define NCAP    64                         // neg candidates per (row,slice)
#define TPOSC   0.99f
#define TNEGC   0.99f

#define NEG_LIST    0
#define NEG_ALLELIG 1
#define NEG_SLOW    2

struct Keys { uint32_t k0[3]; uint32_t k1[3]; };

// per-(row,slice) partials — written unconditionally every run (no init pass)
__device__ float  g_pmax [NROWS * SLICES];   // max iou per slice
__device__ float  g_pomax[NROWS * SLICES];   // max overlap per slice
__device__ int    g_pelig[NROWS * SLICES];
__device__ int    g_pcnt [NROWS * SLICES];
__device__ int    g_ncnt [NROWS * SLICES];
__device__ float  g_posv [NROWS * SLICES * PCAP];
__device__ int    g_posi [NROWS * SLICES * PCAP];
__device__ float  g_negu [NROWS * SLICES * NCAP];
__device__ int    g_negj [NROWS * SLICES * NCAP];

__device__ const float c_POS_T[3] = {0.6f, 0.7f, 0.8f};
__device__ const float c_IOU_T[3] = {0.2f, 0.3f, 0.4f};
__device__ const float c_NEG_T[3] = {0.3f, 0.3f, 0.3f};

// ---------------------------------------------------------------------------
// JAX threefry2x32 (exact; verified rel_err = 0.0)
// ---------------------------------------------------------------------------
__host__ __device__ __forceinline__ void threefry2x32(
    uint32_t k0, uint32_t k1, uint32_t x0, uint32_t x1,
    uint32_t& o0, uint32_t& o1)
{
    uint32_t ks2 = k0 ^ k1 ^ 0x1BD11BDAu;
    x0 += k0; x1 += k1;
#define TFR(r) { x0 += x1; x1 = (x1 << (r)) | (x1 >> (32 - (r))); x1 ^= x0; }
    TFR(13) TFR(15) TFR(26) TFR(6)  x0 += k1;  x1 += ks2 + 1u;
    TFR(17) TFR(29) TFR(16) TFR(24) x0 += ks2; x1 += k0  + 2u;
    TFR(13) TFR(15) TFR(26) TFR(6)  x0 += k0;  x1 += k1  + 3u;
    TFR(17) TFR(29) TFR(16) TFR(24) x0 += k1;  x1 += ks2 + 4u;
    TFR(13) TFR(15) TFR(26) TFR(6)  x0 += ks2; x1 += k0  + 5u;
#undef TFR
    o0 = x0; o1 = x1;
}

__device__ __forceinline__ float u01(uint32_t k0, uint32_t k1, uint32_t idx)
{
    uint32_t a, c;
    threefry2x32(k0, k1, 0u, idx, a, c);
    uint32_t bits = a ^ c;
    return __uint_as_float((bits >> 9) | 0x3F800000u) - 1.0f;
}

// ---------------------------------------------------------------------------
// Block helpers (finalize kernel, 1024 threads)
// ---------------------------------------------------------------------------
__device__ __forceinline__ int block_reduce_sum_int(int v, int* sc)
{
    int tid = threadIdx.x;
    sc[tid] = v; __syncthreads();
    for (int s = A2_TPB / 2; s > 0; s >>= 1) {
        if (tid < s) sc[tid] += sc[tid + s];
        __syncthreads();
    }
    int r = sc[0];
    __syncthreads();
    return r;
}

__device__ void bitonic_desc(float* a)
{
    int tid = threadIdx.x;
    for (int k = 2; k <= A2_TPB; k <<= 1) {
        for (int j = k >> 1; j > 0; j >>= 1) {
            int ixj = tid ^ j;
            if (ixj > tid) {
                float x = a[tid], y = a[ixj];
                bool desc = ((tid & k) == 0);
                if (desc ? (x < y) : (x > y)) { a[tid] = y; a[ixj] = x; }
            }
            __syncthreads();
        }
    }
}

// ---------------------------------------------------------------------------
// Exact fallbacks (statistically never run; guarantee correctness)
// ---------------------------------------------------------------------------
__device__ float kth_bs_iomask(int k, const float* ov, const float* io,
                               float POS_T, int nopos, float mx, int* sc)
{
    unsigned lo = 0u, hi = 0x7F800000u;
    while (hi > lo) {
        unsigned mid = lo + ((hi - lo + 1u) >> 1);
        float t = __uint_as_float(mid);
        int c = 0;
        for (int j = threadIdx.x; j < NROI; j += A2_TPB) {
            float o = ov[j], v = io[j];
            float im = nopos ? ((v >= mx) ? v : 0.0f)
                             : ((o >= POS_T) ? v : 0.0f);
            c += (im >= t);
        }
        c = block_reduce_sum_int(c, sc);
        if (c >= k) lo = mid; else hi = mid - 1u;
    }
    return __uint_as_float(lo);
}

__device__ float kth_bs_score(int k, const float* ov, float NEG_T,
                              uint32_t k0, uint32_t k1, uint32_t rng_base, int* sc)
{
    unsigned lo = 0u, hi = 0x7F800000u;
    while (hi > lo) {
        unsigned mid = lo + ((hi - lo + 1u) >> 1);
        float t = __uint_as_float(mid);
        int c = 0;
        for (int j = threadIdx.x; j < NROI; j += A2_TPB) {
            float o = ov[j];
            if (o <= NEG_T) {
                float u = u01(k0, k1, rng_base + (uint32_t)j);
                c += (u >= t);
            }
        }
        c = block_reduce_sum_int(c, sc);
        if (c >= k) lo = mid; else hi = mid - 1u;
    }
    return __uint_as_float(lo);
}

// ---------------------------------------------------------------------------
// Kernel A: scan + default-fill. grid = NROWS*SLICES = 3072 blocks, 128 thr.
// Streams -1.0f into out for its slice while scanning (coalesced stores).
// ---------------------------------------------------------------------------
__global__ __launch_bounds__(SCAN_TPB)
void scan_kernel(const float* __restrict__ g_ov,
                 const float* __restrict__ g_io,
                 float* __restrict__ g_out,
                 Keys keys)
{
    __shared__ uint16_t s_q[SCAN_WARPS][WCHUNK];   // 8 KB
    __shared__ int   s_cp, s_cn;
    __shared__ float s_wmax[SCAN_WARPS];
    __shared__ float s_womax[SCAN_WARPS];
    __shared__ int   s_welig[SCAN_WARPS];

    const int tid   = threadIdx.x;
    const int wid   = tid >> 5;
    const int lane  = tid & 31;
    const int blk   = blockIdx.x;
    const int r     = blk >> 4;
    const int slice = blk & (SLICES - 1);
    const int h     = r % 3;
    const int b     = r / 3;

    const float POS_T = c_POS_T[h];
    const float NEG_T = c_NEG_T[h];
    const uint32_t k0 = keys.k0[h];
    const uint32_t k1 = keys.k1[h];
    const uint32_t rng_base = (uint32_t)b * (uint32_t)NROI;

    if (tid == 0) { s_cp = 0; s_cn = 0; }
    __syncthreads();

    const int chunk0 = slice * SLICE_ELEMS + wid * WCHUNK;
    const float4* ov4 = (const float4*)(g_ov + (size_t)r * NROI) + (chunk0 >> 2);
    const float4* io4 = (const float4*)(g_io + (size_t)r * NROI) + (chunk0 >> 2);
    float4* out4 = (float4*)(g_out + (size_t)r * NROI) + (chunk0 >> 2);
    const float4 NEG1 = make_float4(-1.0f, -1.0f, -1.0f, -1.0f);

    const unsigned lmask = (1u << lane) - 1u;
    float lmax = 0.0f;     // max iou
    float lomax = 0.0f;    // max overlap  (poscnt>0  <=>  lomax >= POS_T)
    int cnt = 0;

    // ---------- Phase A: scan + compact + default-fill ----------
#pragma unroll 4
    for (int it = 0; it < WCHUNK / 4 / 32; it++) {   // 8 iters
        int q = it * 32 + lane;
        float4 o4 = ov4[q];
        float4 v4 = io4[q];
        out4[q] = NEG1;                              // default label
        int local = q * 4;
#pragma unroll
        for (int l = 0; l < 4; l++) {
            float o = (&o4.x)[l];
            float v = (&v4.x)[l];
            lmax = fmaxf(lmax, v);
            lomax = fmaxf(lomax, o);
            if (v >= TPOSC && o >= POS_T) {          // ~0.4% of elements
                int p = atomicAdd(&s_cp, 1);
                if (p < PCAP) {
                    g_posv[blk * PCAP + p] = v;
                    g_posi[blk * PCAP + p] = chunk0 + local + l;
                }
            }
            bool el = (o <= NEG_T);
            unsigned m = __ballot_sync(0xFFFFFFFFu, el);
            if (el) s_q[wid][cnt + __popc(m & lmask)] = (uint16_t)(local + l);
            cnt += __popc(m);
        }
    }
    __syncwarp();

    // ---------- Phase B: dense hashing of compacted queue ----------
    const uint32_t jwbase = rng_base + (uint32_t)chunk0;
    for (int t = lane; t < cnt; t += 32) {
        uint32_t idx = (uint32_t)s_q[wid][t];
        float u = u01(k0, k1, jwbase + idx);
        if (u >= TNEGC) {                            // ~1% of eligible
            int p = atomicAdd(&s_cn, 1);
            if (p < NCAP) {
                g_negu[blk * NCAP + p] = u;
                g_negj[blk * NCAP + p] = (int)(chunk0 + idx);
            }
        }
    }

    // ---------- reductions ----------
    unsigned wmaxb  = __reduce_max_sync(0xFFFFFFFFu, __float_as_uint(lmax));
    unsigned womaxb = __reduce_max_sync(0xFFFFFFFFu, __float_as_uint(lomax));
    if (lane == 0) {
        s_wmax[wid]  = __uint_as_float(wmaxb);
        s_womax[wid] = __uint_as_float(womaxb);
        s_welig[wid] = cnt;
    }
    __syncthreads();
    if (tid == 0) {
        float mx = 0.0f, omx = 0.0f; int ec = 0;
#pragma unroll
        for (int w = 0; w < SCAN_WARPS; w++) {
            mx = fmaxf(mx, s_wmax[w]);
            omx = fmaxf(omx, s_womax[w]);
            ec += s_welig[w];
        }
        g_pmax[blk] = mx;
        g_pomax[blk] = omx;
        g_pelig[blk] = ec;
        g_pcnt[blk] = s_cp;
        g_ncnt[blk] = s_cn;
    }
}

// ---------------------------------------------------------------------------
// Kernel B: per-row finalize + scatter. grid = NROWS, 1024 threads.
// Fast path: scatter ~65 stores over the -1 default. Slow path (statistically
// never): the block rewrites its whole row exactly.
// ---------------------------------------------------------------------------
__global__ __launch_bounds__(A2_TPB)
void finalize_kernel(const float* __restrict__ g_ov,
                     const float* __restrict__ g_io,
                     const float* __restrict__ g_nm,
                     float* __restrict__ g_out,
                     Keys keys)
{
    __shared__ float s_sort[A2_TPB];
    __shared__ int   s_pcnt[SLICES], s_ncnt[SLICES];
    __shared__ float s_mxs[SLICES], s_omxs[SLICES];
    __shared__ int   s_eligs[SLICES];
    __shared__ float s_mx, s_omx;
    __shared__ int   s_eligcnt, s_cp, s_cn, s_ovfP, s_ovfN;

    const int tid = threadIdx.x;
    const int r = blockIdx.x;
    const int h = r % 3;
    const int b = r / 3;

    const float POS_T = c_POS_T[h];
    const float NEG_T = c_NEG_T[h];
    const float IOU_T = c_IOU_T[h];
    const uint32_t k0 = keys.k0[h];
    const uint32_t k1 = keys.k1[h];
    const uint32_t rng_base = (uint32_t)b * (uint32_t)NROI;

    const float* ov = g_ov + (size_t)r * NROI;
    const float* io = g_io + (size_t)r * NROI;
    const float* nm = g_nm + (size_t)r * NROI;
    float*       out = g_out + (size_t)r * NROI;

    if (tid < SLICES) {
        int blk = r * SLICES + tid;
        s_pcnt[tid] = g_pcnt[blk];
        s_ncnt[tid] = g_ncnt[blk];
        s_mxs[tid]  = g_pmax[blk];
        s_omxs[tid] = g_pomax[blk];
        s_eligs[tid]= g_pelig[blk];
    }
    __syncthreads();
    if (tid == 0) {
        float mx = 0.0f, omx = 0.0f; int ec = 0, cp = 0, cn = 0, op = 0, on = 0;
#pragma unroll
        for (int s = 0; s < SLICES; s++) {
            mx = fmaxf(mx, s_mxs[s]); omx = fmaxf(omx, s_omxs[s]);
            ec += s_eligs[s];
            cp += s_pcnt[s]; cn += s_ncnt[s];
            op |= (s_pcnt[s] > PCAP); on |= (s_ncnt[s] > NCAP);
        }
        s_mx = mx; s_omx = omx; s_eligcnt = ec;
        s_cp = cp; s_cn = cn; s_ovfP = op; s_ovfN = on;
    }
    __syncthreads();

    const float mx = s_mx;
    const int eligcnt = s_eligcnt;
    const int cp = s_cp, cn = s_cn, ovfP = s_ovfP, ovfN = s_ovfN;
    const int nopos = (s_omx < POS_T);       // poscnt == 0  <=>  max(ov) < POS_T

    // -------- positive threshold: 16th (+2nd) largest of iou_masked --------
    int posfast = 0;
    float t16, top2 = 0.0f;
    // candidate regs (slice layout: SLICES*PCAP = 1024 = A2_TPB)
    const int psl = tid >> 6, pi = tid & (PCAP - 1);
    const bool pvalid = (pi < s_pcnt[psl]);
    float pv_reg = pvalid ? g_posv[(r * SLICES + psl) * PCAP + pi] : -1.0f;
    int   pj_reg = pvalid ? g_posi[(r * SLICES + psl) * PCAP + pi] : 0;

    if (!nopos && cp >= 16 && !ovfP) {
        posfast = 1;
        s_sort[tid] = pv_reg;
        __syncthreads();
        bitonic_desc(s_sort);
        t16 = s_sort[15];
        top2 = s_sort[1];
        __syncthreads();
    } else {
        t16 = kth_bs_iomask(16, ov, io, POS_T, nopos, mx, (int*)s_sort);
        if (h == 0) top2 = kth_bs_iomask(2, ov, io, POS_T, nopos, mx, (int*)s_sort);
    }
    float tk = (t16 >= IOU_T) ? t16 : IOU_T;

    // -------- negative threshold: 48th largest random score among eligible --
    float kth = -1.0f;
    int negmode;
    const int nsl = tid >> 6, ni = tid & (NCAP - 1);
    const bool nvalid = (ni < s_ncnt[nsl]);
    float nu_reg = nvalid ? g_negu[(r * SLICES + nsl) * NCAP + ni] : -1.0f;
    int   nj_reg = nvalid ? g_negj[(r * SLICES + nsl) * NCAP + ni] : 0;

    if (eligcnt < 48) {
        negmode = NEG_ALLELIG;               // kth = -inf: all eligible neg
    } else if (cn >= 48 && !ovfN) {
        negmode = NEG_LIST;
        s_sort[tid] = nu_reg;
        __syncthreads();
        bitonic_desc(s_sort);
        kth = s_sort[47];
        __syncthreads();
    } else {
        negmode = NEG_SLOW;
        kth = kth_bs_score(48, ov, NEG_T, k0, k1, rng_base, (int*)s_sort);
    }

    // ---------------- fast path: scatter over -1 default ----------------
    if (posfast && negmode == NEG_LIST) {
        // negatives: label = -1 + 1 = 0  (disjoint from pos: o<=0.3 vs o>=POS_T)
        if (nvalid && nu_reg >= kth)
            out[nj_reg] = 0.0f;
        // positives: label = -1 + 2*nm[j]
        bool posb = pvalid && ((pv_reg >= tk) || (h == 0 && pv_reg > top2));
        if (posb)
            out[pj_reg] = -1.0f + 2.0f * nm[pj_reg];
        return;
    }

    // ---------------- slow path: rewrite whole row exactly ----------------
    const float4* ov4 = (const float4*)ov;
    const float4* io4 = (const float4*)io;
    float4* out4 = (float4*)out;
    for (int q = tid; q < NROI / 4; q += A2_TPB) {
        float4 o4 = ov4[q];
        float4 v4 = io4[q];
        float4 res;
#pragma unroll
        for (int l = 0; l < 4; l++) {
            int j = q * 4 + l;
            float o = (&o4.x)[l];
            float v = (&v4.x)[l];
            float im = nopos ? ((v >= mx) ? v : 0.0f)
                             : ((o >= POS_T) ? v : 0.0f);
            bool posb = (im >= tk);
            if (h == 0) posb = posb || (im > top2);
            float posf = 0.0f;
            if (posb) posf = nm[j];

            float negf = 0.0f;
            if (o <= NEG_T) {
                if (negmode == NEG_ALLELIG) {
                    negf = 1.0f;
                } else {
                    // NEG_LIST / NEG_SLOW: exact kth; recomputed u matches list
                    float u = u01(k0, k1, rng_base + (uint32_t)j);
                    if (u >= kth) negf = 1.0f;
                }
            }
            (&res.x)[l] = (-1.0f + negf) + 2.0f * posf;
        }
        out4[q] = res;
    }
}

// ---------------------------------------------------------------------------
// Launch
// ---------------------------------------------------------------------------
extern "C" void kernel_launch(void* const* d_in, const int* in_sizes, int n_in,
                              void* d_out, int out_size)
{
    const float* ov = (const float*)d_in[0];
    const float* io = (const float*)d_in[1];
    const float* nm = (const float*)d_in[2];
    float* out = (float*)d_out;

    Keys keys;
    for (int h = 0; h < NCASC; h++) {
        uint32_t a, c;
        threefry2x32(0u, 42u, 0u, (uint32_t)h, a, c);
        keys.k0[h] = a;
        keys.k1[h] = c;
    }

    scan_kernel<<<NROWS * SLICES, SCAN_TPB>>>(ov, io, out, keys);
    finalize_kernel<<<NROWS, A2_TPB>>>(ov, io, nm, out, keys);
}

// round 10
// speedup vs baseline: 1.4991x; 1.1538x over previous
#include <cuda_runtime.h>
#include <stdint.h>

#define NROI    65536
#define NCASC   3
#define NBATCH  64
#define NROWS   (NBATCH * NCASC)
#define SLICES  16
#define SLICE_ELEMS (NROI / SLICES)        // 4096
#define SCAN_TPB 128
#define SCAN_WARPS (SCAN_TPB / 32)         // 4
#define WCHUNK  (SLICE_ELEMS / SCAN_WARPS) // 1024 elements per warp
#define A2_TPB  1024
#define PCAP    64                         // pos candidates per (row,slice)
#define NCAP    64                         // neg candidates per (row,slice)
#define TPOSC   0.99f
#define TNEGC   0.99f
#define BITS_CAND 0x3F7AE148u              // bits(0.98) — safe lower bound
#define BITS_ONE  0x3F800000u              // bits(1.0)  — values strictly below

#define NEG_LIST    0
#define NEG_ALLELIG 1
#define NEG_SLOW    2

struct Keys { uint32_t k0[3]; uint32_t k1[3]; };

// per-(row,slice) partials — written unconditionally every run (no init pass)
__device__ float  g_pmax [NROWS * SLICES];   // max iou per slice
__device__ float  g_pomax[NROWS * SLICES];   // max overlap per slice
__device__ int    g_pelig[NROWS * SLICES];
__device__ int    g_pcnt [NROWS * SLICES];
__device__ int    g_ncnt [NROWS * SLICES];
__device__ float  g_posv [NROWS * SLICES * PCAP];
__device__ int    g_posi [NROWS * SLICES * PCAP];
__device__ float  g_negu [NROWS * SLICES * NCAP];
__device__ int    g_negj [NROWS * SLICES * NCAP];

__device__ const float c_POS_T[3] = {0.6f, 0.7f, 0.8f};
__device__ const float c_IOU_T[3] = {0.2f, 0.3f, 0.4f};
__device__ const float c_NEG_T[3] = {0.3f, 0.3f, 0.3f};

// ---------------------------------------------------------------------------
// JAX threefry2x32 (exact; verified rel_err = 0.0)
// ---------------------------------------------------------------------------
__host__ __device__ __forceinline__ void threefry2x32(
    uint32_t k0, uint32_t k1, uint32_t x0, uint32_t x1,
    uint32_t& o0, uint32_t& o1)
{
    uint32_t ks2 = k0 ^ k1 ^ 0x1BD11BDAu;
    x0 += k0; x1 += k1;
#define TFR(r) { x0 += x1; x1 = (x1 << (r)) | (x1 >> (32 - (r))); x1 ^= x0; }
    TFR(13) TFR(15) TFR(26) TFR(6)  x0 += k1;  x1 += ks2 + 1u;
    TFR(17) TFR(29) TFR(16) TFR(24) x0 += ks2; x1 += k0  + 2u;
    TFR(13) TFR(15) TFR(26) TFR(6)  x0 += k0;  x1 += k1  + 3u;
    TFR(17) TFR(29) TFR(16) TFR(24) x0 += k1;  x1 += ks2 + 4u;
    TFR(13) TFR(15) TFR(26) TFR(6)  x0 += ks2; x1 += k0  + 5u;
#undef TFR
    o0 = x0; o1 = x1;
}

__device__ __forceinline__ float u01(uint32_t k0, uint32_t k1, uint32_t idx)
{
    uint32_t a, c;
    threefry2x32(k0, k1, 0u, idx, a, c);
    uint32_t bits = a ^ c;
    return __uint_as_float((bits >> 9) | 0x3F800000u) - 1.0f;
}

// ---------------------------------------------------------------------------
// kth-largest via binary search on float bit patterns, counting with
// __syncthreads_count (block-wide, no smem, no sort). Exact.
// Precondition: count(myval >= uint_as_float(lo)) >= k  (block-uniform args).
// ---------------------------------------------------------------------------
__device__ float block_kth(int k, float myval, unsigned lo, unsigned hi)
{
    while (hi > lo) {
        unsigned mid = lo + ((hi - lo + 1u) >> 1);
        int c = __syncthreads_count(myval >= __uint_as_float(mid));
        if (c >= k) lo = mid; else hi = mid - 1u;
    }
    return __uint_as_float(lo);
}

// ---------------------------------------------------------------------------
// Exact fallbacks over the full row (statistically never run)
// ---------------------------------------------------------------------------
__device__ float kth_bs_iomask(int k, const float* ov, const float* io,
                               float POS_T, int nopos, float mx)
{
    unsigned lo = 0u, hi = 0x7F800000u;
    while (hi > lo) {
        unsigned mid = lo + ((hi - lo + 1u) >> 1);
        float t = __uint_as_float(mid);
        int c = 0;
        for (int j = threadIdx.x; j < NROI; j += A2_TPB) {
            float o = ov[j], v = io[j];
            float im = nopos ? ((v >= mx) ? v : 0.0f)
                             : ((o >= POS_T) ? v : 0.0f);
            c += (im >= t);
        }
        // block-wide sum via ballot-free count of a loop? use warp reduce + count
        c = __reduce_add_sync(0xFFFFFFFFu, (unsigned)c);
        // one count per warp -> combine via syncthreads_count over bits
        // simpler: serialize through shared is avoided; use iterative count:
        // count threads whose warp-leader sum exceeds... instead do per-thread
        // contribution trick: count (c > t_i) is wrong. Use plain approach:
        __shared__ int s_ws[32];
        if ((threadIdx.x & 31) == 0) s_ws[threadIdx.x >> 5] = c;
        __syncthreads();
        if (threadIdx.x == 0) {
            int tot = 0;
            for (int w = 0; w < A2_TPB / 32; w++) tot += s_ws[w];
            s_ws[0] = tot;
        }
        __syncthreads();
        c = s_ws[0];
        __syncthreads();
        if (c >= k) lo = mid; else hi = mid - 1u;
    }
    return __uint_as_float(lo);
}

__device__ float kth_bs_score(int k, const float* ov, float NEG_T,
                              uint32_t k0, uint32_t k1, uint32_t rng_base)
{
    unsigned lo = 0u, hi = 0x7F800000u;
    while (hi > lo) {
        unsigned mid = lo + ((hi - lo + 1u) >> 1);
        float t = __uint_as_float(mid);
        int c = 0;
        for (int j = threadIdx.x; j < NROI; j += A2_TPB) {
            float o = ov[j];
            if (o <= NEG_T) {
                float u = u01(k0, k1, rng_base + (uint32_t)j);
                c += (u >= t);
            }
        }
        c = __reduce_add_sync(0xFFFFFFFFu, (unsigned)c);
        __shared__ int s_ws[32];
        if ((threadIdx.x & 31) == 0) s_ws[threadIdx.x >> 5] = c;
        __syncthreads();
        if (threadIdx.x == 0) {
            int tot = 0;
            for (int w = 0; w < A2_TPB / 32; w++) tot += s_ws[w];
            s_ws[0] = tot;
        }
        __syncthreads();
        c = s_ws[0];
        __syncthreads();
        if (c >= k) lo = mid; else hi = mid - 1u;
    }
    return __uint_as_float(lo);
}

// ---------------------------------------------------------------------------
// Kernel A: scan + default-fill. grid = NROWS*SLICES = 3072 blocks, 128 thr.
// (unchanged from R9 — matched the model)
// ---------------------------------------------------------------------------
__global__ __launch_bounds__(SCAN_TPB)
void scan_kernel(const float* __restrict__ g_ov,
                 const float* __restrict__ g_io,
                 float* __restrict__ g_out,
                 Keys keys)
{
    __shared__ uint16_t s_q[SCAN_WARPS][WCHUNK];   // 8 KB
    __shared__ int   s_cp, s_cn;
    __shared__ float s_wmax[SCAN_WARPS];
    __shared__ float s_womax[SCAN_WARPS];
    __shared__ int   s_welig[SCAN_WARPS];

    const int tid   = threadIdx.x;
    const int wid   = tid >> 5;
    const int lane  = tid & 31;
    const int blk   = blockIdx.x;
    const int r     = blk >> 4;
    const int slice = blk & (SLICES - 1);
    const int h     = r % 3;
    const int b     = r / 3;

    const float POS_T = c_POS_T[h];
    const float NEG_T = c_NEG_T[h];
    const uint32_t k0 = keys.k0[h];
    const uint32_t k1 = keys.k1[h];
    const uint32_t rng_base = (uint32_t)b * (uint32_t)NROI;

    if (tid == 0) { s_cp = 0; s_cn = 0; }
    __syncthreads();

    const int chunk0 = slice * SLICE_ELEMS + wid * WCHUNK;
    const float4* ov4 = (const float4*)(g_ov + (size_t)r * NROI) + (chunk0 >> 2);
    const float4* io4 = (const float4*)(g_io + (size_t)r * NROI) + (chunk0 >> 2);
    float4* out4 = (float4*)(g_out + (size_t)r * NROI) + (chunk0 >> 2);
    const float4 NEG1 = make_float4(-1.0f, -1.0f, -1.0f, -1.0f);

    const unsigned lmask = (1u << lane) - 1u;
    float lmax = 0.0f;     // max iou
    float lomax = 0.0f;    // max overlap  (poscnt>0  <=>  lomax >= POS_T)
    int cnt = 0;

    // ---------- Phase A: scan + compact + default-fill ----------
#pragma unroll 4
    for (int it = 0; it < WCHUNK / 4 / 32; it++) {   // 8 iters
        int q = it * 32 + lane;
        float4 o4 = ov4[q];
        float4 v4 = io4[q];
        out4[q] = NEG1;                              // default label
        int local = q * 4;
#pragma unroll
        for (int l = 0; l < 4; l++) {
            float o = (&o4.x)[l];
            float v = (&v4.x)[l];
            lmax = fmaxf(lmax, v);
            lomax = fmaxf(lomax, o);
            if (v >= TPOSC && o >= POS_T) {          // ~0.4% of elements
                int p = atomicAdd(&s_cp, 1);
                if (p < PCAP) {
                    g_posv[blk * PCAP + p] = v;
                    g_posi[blk * PCAP + p] = chunk0 + local + l;
                }
            }
            bool el = (o <= NEG_T);
            unsigned m = __ballot_sync(0xFFFFFFFFu, el);
            if (el) s_q[wid][cnt + __popc(m & lmask)] = (uint16_t)(local + l);
            cnt += __popc(m);
        }
    }
    __syncwarp();

    // ---------- Phase B: dense hashing of compacted queue ----------
    const uint32_t jwbase = rng_base + (uint32_t)chunk0;
    for (int t = lane; t < cnt; t += 32) {
        uint32_t idx = (uint32_t)s_q[wid][t];
        float u = u01(k0, k1, jwbase + idx);
        if (u >= TNEGC) {                            // ~1% of eligible
            int p = atomicAdd(&s_cn, 1);
            if (p < NCAP) {
                g_negu[blk * NCAP + p] = u;
                g_negj[blk * NCAP + p] = (int)(chunk0 + idx);
            }
        }
    }

    // ---------- reductions ----------
    unsigned wmaxb  = __reduce_max_sync(0xFFFFFFFFu, __float_as_uint(lmax));
    unsigned womaxb = __reduce_max_sync(0xFFFFFFFFu, __float_as_uint(lomax));
    if (lane == 0) {
        s_wmax[wid]  = __uint_as_float(wmaxb);
        s_womax[wid] = __uint_as_float(womaxb);
        s_welig[wid] = cnt;
    }
    __syncthreads();
    if (tid == 0) {
        float mx = 0.0f, omx = 0.0f; int ec = 0;
#pragma unroll
        for (int w = 0; w < SCAN_WARPS; w++) {
            mx = fmaxf(mx, s_wmax[w]);
            omx = fmaxf(omx, s_womax[w]);
            ec += s_welig[w];
        }
        g_pmax[blk] = mx;
        g_pomax[blk] = omx;
        g_pelig[blk] = ec;
        g_pcnt[blk] = s_cp;
        g_ncnt[blk] = s_cn;
    }
}

// ---------------------------------------------------------------------------
// Kernel B: per-row finalize + scatter. grid = NROWS, 1024 threads.
// Order statistics via __syncthreads_count binary search (no sorts).
// ---------------------------------------------------------------------------
__global__ __launch_bounds__(A2_TPB)
void finalize_kernel(const float* __restrict__ g_ov,
                     const float* __restrict__ g_io,
                     const float* __restrict__ g_nm,
                     float* __restrict__ g_out,
                     Keys keys)
{
    __shared__ int   s_pcnt[SLICES], s_ncnt[SLICES];
    __shared__ float s_mxs[SLICES], s_omxs[SLICES];
    __shared__ int   s_eligs[SLICES];
    __shared__ float s_mx, s_omx;
    __shared__ int   s_eligcnt, s_cp, s_cn, s_ovfP, s_ovfN;

    const int tid = threadIdx.x;
    const int r = blockIdx.x;
    const int h = r % 3;
    const int b = r / 3;

    const float POS_T = c_POS_T[h];
    const float NEG_T = c_NEG_T[h];
    const float IOU_T = c_IOU_T[h];
    const uint32_t k0 = keys.k0[h];
    const uint32_t k1 = keys.k1[h];
    const uint32_t rng_base = (uint32_t)b * (uint32_t)NROI;

    const float* ov = g_ov + (size_t)r * NROI;
    const float* io = g_io + (size_t)r * NROI;
    const float* nm = g_nm + (size_t)r * NROI;
    float*       out = g_out + (size_t)r * NROI;

    if (tid < SLICES) {
        int blk = r * SLICES + tid;
        s_pcnt[tid] = g_pcnt[blk];
        s_ncnt[tid] = g_ncnt[blk];
        s_mxs[tid]  = g_pmax[blk];
        s_omxs[tid] = g_pomax[blk];
        s_eligs[tid]= g_pelig[blk];
    }
    __syncthreads();
    if (tid == 0) {
        float mx = 0.0f, omx = 0.0f; int ec = 0, cp = 0, cn = 0, op = 0, on = 0;
#pragma unroll
        for (int s = 0; s < SLICES; s++) {
            mx = fmaxf(mx, s_mxs[s]); omx = fmaxf(omx, s_omxs[s]);
            ec += s_eligs[s];
            cp += s_pcnt[s]; cn += s_ncnt[s];
            op |= (s_pcnt[s] > PCAP); on |= (s_ncnt[s] > NCAP);
        }
        s_mx = mx; s_omx = omx; s_eligcnt = ec;
        s_cp = cp; s_cn = cn; s_ovfP = op; s_ovfN = on;
    }
    __syncthreads();

    const float mx = s_mx;
    const int eligcnt = s_eligcnt;
    const int cp = s_cp, cn = s_cn, ovfP = s_ovfP, ovfN = s_ovfN;
    const int nopos = (s_omx < POS_T);       // poscnt == 0  <=>  max(ov) < POS_T

    // candidate regs (slice layout: SLICES*PCAP = 1024 = A2_TPB)
    const int psl = tid >> 6, pi = tid & (PCAP - 1);
    const bool pvalid = (pi < s_pcnt[psl]);
    float pv_reg = pvalid ? g_posv[(r * SLICES + psl) * PCAP + pi] : -1.0f;
    int   pj_reg = pvalid ? g_posi[(r * SLICES + psl) * PCAP + pi] : 0;

    const int nsl = tid >> 6, ni = tid & (NCAP - 1);
    const bool nvalid = (ni < s_ncnt[nsl]);
    float nu_reg = nvalid ? g_negu[(r * SLICES + nsl) * NCAP + ni] : -1.0f;
    int   nj_reg = nvalid ? g_negj[(r * SLICES + nsl) * NCAP + ni] : 0;

    // -------- positive threshold: 16th (+2nd) largest of iou_masked --------
    // All candidates >= TPOSC, so the kth lies in [BITS_CAND, BITS_ONE).
    int posfast = 0;
    float t16, top2 = 0.0f;
    if (!nopos && cp >= 16 && !ovfP) {
        posfast = 1;
        t16 = block_kth(16, pv_reg, BITS_CAND, BITS_ONE);
        if (h == 0) top2 = block_kth(2, pv_reg, BITS_CAND, BITS_ONE);
    } else {
        t16 = kth_bs_iomask(16, ov, io, POS_T, nopos, mx);
        if (h == 0) top2 = kth_bs_iomask(2, ov, io, POS_T, nopos, mx);
    }
    float tk = (t16 >= IOU_T) ? t16 : IOU_T;

    // -------- negative threshold: 48th largest random score among eligible --
    float kth = -1.0f;
    int negmode;
    if (eligcnt < 48) {
        negmode = NEG_ALLELIG;               // kth = -inf: all eligible neg
    } else if (cn >= 48 && !ovfN) {
        negmode = NEG_LIST;
        kth = block_kth(48, nu_reg, BITS_CAND, BITS_ONE);
    } else {
        negmode = NEG_SLOW;
        kth = kth_bs_score(48, ov, NEG_T, k0, k1, rng_base);
    }

    // ---------------- fast path: scatter over -1 default ----------------
    if (posfast && negmode == NEG_LIST) {
        // negatives: label = -1 + 1 = 0  (disjoint from pos: o<=0.3 vs o>=POS_T)
        if (nvalid && nu_reg >= kth)
            out[nj_reg] = 0.0f;
        // positives: label = -1 + 2*nm[j]
        bool posb = pvalid && ((pv_reg >= tk) || (h == 0 && pv_reg > top2));
        if (posb)
            out[pj_reg] = -1.0f + 2.0f * nm[pj_reg];
        return;
    }

    // ---------------- slow path: rewrite whole row exactly ----------------
    const float4* ov4 = (const float4*)ov;
    const float4* io4 = (const float4*)io;
    float4* out4 = (float4*)out;
    for (int q = tid; q < NROI / 4; q += A2_TPB) {
        float4 o4 = ov4[q];
        float4 v4 = io4[q];
        float4 res;
#pragma unroll
        for (int l = 0; l < 4; l++) {
            int j = q * 4 + l;
            float o = (&o4.x)[l];
            float v = (&v4.x)[l];
            float im = nopos ? ((v >= mx) ? v : 0.0f)
                             : ((o >= POS_T) ? v : 0.0f);
            bool posb = (im >= tk);
            if (h == 0) posb = posb || (im > top2);
            float posf = 0.0f;
            if (posb) posf = nm[j];

            float negf = 0.0f;
            if (o <= NEG_T) {
                if (negmode == NEG_ALLELIG) {
                    negf = 1.0f;
                } else {
                    // NEG_LIST / NEG_SLOW: exact kth; recomputed u matches list
                    float u = u01(k0, k1, rng_base + (uint32_t)j);
                    if (u >= kth) negf = 1.0f;
                }
            }
            (&res.x)[l] = (-1.0f + negf) + 2.0f * posf;
        }
        out4[q] = res;
    }
}

// ---------------------------------------------------------------------------
// Launch
// ---------------------------------------------------------------------------
extern "C" void kernel_launch(void* const* d_in, const int* in_sizes, int n_in,
                              void* d_out, int out_size)
{
    const float* ov = (const float*)d_in[0];
    const float* io = (const float*)d_in[1];
    const float* nm = (const float*)d_in[2];
    float* out = (float*)d_out;

    Keys keys;
    for (int h = 0; h < NCASC; h++) {
        uint32_t a, c;
        threefry2x32(0u, 42u, 0u, (uint32_t)h, a, c);
        keys.k0[h] = a;
        keys.k1[h] = c;
    }

    scan_kernel<<<NROWS * SLICES, SCAN_TPB>>>(ov, io, out, keys);
    finalize_kernel<<<NROWS, A2_TPB>>>(ov, io, nm, out, keys);
}